// round 11
// baseline (speedup 1.0000x reference)
#include <cuda_runtime.h>

// out[b, H-1-h, w] = exp(EPS)*o[0] + sum_{d=1}^{D-1} (prod_{k<d}(1-o[k])) * o[d]
// o = clip(v, EPS, 1-EPS).
//
// Monolithic scalar-per-thread scan with EARLY RAY TERMINATION (bounded-error):
// with T_0 = 1 the partial sum telescopes: a_k = 1 - T_k (modulo the exp(EPS)
// factors, which only multiply terms by 1+1e-5), and the neglected tail is
//   sum_{d>=k} T_d o_d = T_k - T_D <= T_k.
// So at exit out >= 1 - T_k and abs err <= T_k, giving per-element rel err
// <= TCUT/(1-TCUT) ~= TCUT = 1e-5 -- 100x under the 1e-3 tolerance, and
// input-independent (if T never drops below TCUT we simply scan all 128).
//
// Layout: 262144 threads, one float-column (ray) each; a warp covers 32
// consecutive w -> one contiguous 128B line per depth slice. Depth walked in
// chunks of 8 with all 8 loads batched (MLP=8); warp vote every 4 elements.
// Plain loads (NOT __ldcs): the ~22MB live working set is L2-resident across
// graph replays and we want to keep it there.

#define EPSF       1e-5f
#define ONE_MEPS   (1.0f - 1e-5f)
#define EXP_EPS_M1 1.00000500002e-5f    // expf(1e-5f) - 1
#define TCUT       1e-5f

#define D_     128
#define H_     128
#define W_     128
#define SLICE  (H_ * W_)                // floats per depth slice (16384)

static __device__ __forceinline__ float clipv(float v) {
    return fminf(fmaxf(v, EPSF), ONE_MEPS);
}

__global__ void __launch_bounds__(128)
eff_loss_kernel(const float* __restrict__ vox, float* __restrict__ out) {
    int tid = blockIdx.x * blockDim.x + threadIdx.x;   // 262144 rays
    int w = tid & (W_ - 1);
    int h = (tid >> 7) & (H_ - 1);
    int b =  tid >> 14;

    const float* p = vox + (size_t)b * D_ * SLICE + (size_t)h * W_ + w;

    float a = 0.0f, T = 1.0f, o0 = 0.0f;

    for (int base = 0; base < D_; base += 8) {
        // batch the 8 independent loads of this chunk (MLP=8)
        float v[8];
        #pragma unroll
        for (int j = 0; j < 8; ++j)
            v[j] = p[(size_t)(base + j) * SLICE];

        bool done = false;
        #pragma unroll
        for (int half = 0; half < 2; ++half) {
            #pragma unroll
            for (int j = 0; j < 4; ++j) {
                float o = clipv(v[half * 4 + j]);
                if (base == 0 && half == 0 && j == 0) o0 = o;
                a = fmaf(T, o, a);        // accumulate termination prob
                T = fmaf(-o, T, T);       // T *= (1 - o)
            }
            // early ray termination: tail mass <= T for every lane
            if (__all_sync(0xffffffffu, T < TCUT)) { done = true; break; }
        }
        if (done) break;
    }

    // d=0 term carries weight exp(EPS) instead of 1
    a = fmaf(EXP_EPS_M1, o0, a);

    // vertical flip on h
    out[(size_t)b * SLICE + (size_t)(H_ - 1 - h) * W_ + w] = a;
}

extern "C" void kernel_launch(void* const* d_in, const int* in_sizes, int n_in,
                              void* d_out, int out_size) {
    const float* vox = (const float*)d_in[0];
    float* out = (float*)d_out;
    constexpr int TOTAL = 16 * H_ * W_;     // 262144 threads
    eff_loss_kernel<<<TOTAL / 128, 128>>>(vox, out);
}

// round 13
// speedup vs baseline: 1.2917x; 1.2917x over previous
#include <cuda_runtime.h>

// out[b, H-1-h, w] = exp(EPS)*o[0] + sum_{d=1}^{D-1} (prod_{k<d}(1-o[k])) * o[d]
// o = clip(v, EPS, 1-EPS).
//
// Scalar-per-thread scan with bounded-error early ray termination:
// tail mass after k slices is <= T_k and out >= 1 - T_k, so exiting when all
// lanes have T < TCUT=1e-5 bounds per-element rel err by ~1e-5 (100x under
// the 1e-3 tolerance), input-independent (worst case scans all 128 slices).
//
// Latency shape: measured warp-max exit depth is ~22 slices, so the FIRST
// batch loads 20 slices in one fully-batched burst (20 independent LDG,
// MLP=20 -> ONE memory round trip for the common case), computes, votes
// once. Surviving warps continue in 8-slice batched chunks.
// Warp = 32 consecutive w -> each slice access is one contiguous 128B line.

#define EPSF       1e-5f
#define ONE_MEPS   (1.0f - 1e-5f)
#define EXP_EPS_M1 1.00000500002e-5f    // expf(1e-5f) - 1
#define TCUT       1e-5f

#define D_     128
#define H_     128
#define W_     128
#define SLICE  (H_ * W_)                // floats per depth slice (16384)
#define FIRST  20                       // first-batch depth (covers ~typical exit)

static __device__ __forceinline__ float clipv(float v) {
    return fminf(fmaxf(v, EPSF), ONE_MEPS);
}

__global__ void __launch_bounds__(128)
eff_loss_kernel(const float* __restrict__ vox, float* __restrict__ out) {
    int tid = blockIdx.x * blockDim.x + threadIdx.x;   // 262144 rays
    int w = tid & (W_ - 1);
    int h = (tid >> 7) & (H_ - 1);
    int b =  tid >> 14;

    const float* p = vox + (size_t)b * D_ * SLICE + (size_t)h * W_ + w;

    // ---- first batch: FIRST slices, all loads issued before any compute ----
    float v[FIRST];
    #pragma unroll
    for (int j = 0; j < FIRST; ++j)
        v[j] = p[(size_t)j * SLICE];

    float a = 0.0f, T = 1.0f, o0;
    o0 = clipv(v[0]);
    #pragma unroll
    for (int j = 0; j < FIRST; ++j) {
        float o = clipv(v[j]);
        a = fmaf(T, o, a);        // accumulate termination prob
        T = fmaf(-o, T, T);       // T *= (1 - o)
    }

    // ---- continuation: 8-slice batched chunks with per-chunk vote ----
    if (!__all_sync(0xffffffffu, T < TCUT)) {
        for (int base = FIRST; base < D_; base += 8) {
            float u[8];
            #pragma unroll
            for (int j = 0; j < 8; ++j)
                u[j] = p[(size_t)(base + j) * SLICE];
            #pragma unroll
            for (int j = 0; j < 8; ++j) {
                float o = clipv(u[j]);
                a = fmaf(T, o, a);
                T = fmaf(-o, T, T);
            }
            if (__all_sync(0xffffffffu, T < TCUT)) break;
        }
    }

    // d=0 term carries weight exp(EPS) instead of 1
    a = fmaf(EXP_EPS_M1, o0, a);

    // vertical flip on h
    out[(size_t)b * SLICE + (size_t)(H_ - 1 - h) * W_ + w] = a;
}

extern "C" void kernel_launch(void* const* d_in, const int* in_sizes, int n_in,
                              void* d_out, int out_size) {
    const float* vox = (const float*)d_in[0];
    float* out = (float*)d_out;
    constexpr int TOTAL = 16 * H_ * W_;     // 262144 threads
    eff_loss_kernel<<<TOTAL / 128, 128>>>(vox, out);
}